// round 13
// baseline (speedup 1.0000x reference)
#include <cuda_runtime.h>
#include <cstdint>

#define NB      8
#define NHEADS  12
#define HH      24
#define SEQ     576
#define DIM     64
#define NPOS    24
#define BATCH   96

// Scratch: pe_x_flat / pe_y_flat  [BATCH][SEQ][NPOS]
__device__ __align__(16) float g_Vx[BATCH * SEQ * NPOS];
__device__ __align__(16) float g_Vy[BATCH * SEQ * NPOS];

__device__ __forceinline__ float sigmoidf_(float x) {
    return 1.0f / (1.0f + __expf(-x));
}

__device__ __forceinline__ unsigned long long fma2(unsigned long long a,
                                                   unsigned long long b,
                                                   unsigned long long c) {
    unsigned long long d;
    asm("fma.rn.f32x2 %0, %1, %2, %3;" : "=l"(d) : "l"(a), "l"(b), "l"(c));
    return d;
}

__device__ __forceinline__ unsigned long long pack2(float lo, float hi) {
    unsigned long long r;
    asm("mov.b64 %0, {%1, %2};" : "=l"(r) : "f"(lo), "f"(hi));
    return r;
}

__device__ __forceinline__ float fsqrt_approx(float x) {
    float r;
    asm("sqrt.approx.f32 %0, %1;" : "=f"(r) : "f"(x));
    return r;
}

__device__ __forceinline__ uint32_t f2tf32(float v) {
    uint32_t r;
    asm("cvt.rna.tf32.f32 %0, %1;" : "=r"(r) : "f"(v));
    return r;
}

__device__ __forceinline__ void mma_tf32(float* c, const uint32_t* a, uint32_t b0, uint32_t b1) {
    asm volatile(
        "mma.sync.aligned.m16n8k8.row.col.f32.tf32.tf32.f32 "
        "{%0,%1,%2,%3}, {%4,%5,%6,%7}, {%8,%9}, {%0,%1,%2,%3};"
        : "+f"(c[0]), "+f"(c[1]), "+f"(c[2]), "+f"(c[3])
        : "r"(a[0]), "r"(a[1]), "r"(a[2]), "r"(a[3]), "r"(b0), "r"(b1));
}

// ---------------------------------------------------------------------------
// Kernel 1: fused CoPE (EXACT R12 form — measured ~48 us).
// ---------------------------------------------------------------------------
__global__ void __launch_bounds__(512) cope_kernel(
    const float* __restrict__ query,      // [8,12,576,64]
    const float* __restrict__ attn,       // [8,12,576,576]
    const float* __restrict__ pex,        // [64,24]
    const float* __restrict__ pey)        // [64,24]
{
    __shared__ __align__(16) float q_s[2][HH * 68];
    __shared__ __align__(16) float pe_s[2][DIM * NPOS];
    __shared__ __align__(8)  float li[2][HH * 26];

    int t    = threadIdx.x;
    int path = t >> 8;
    int tp   = t & 255;

    int id   = blockIdx.x;
    int n    = id / 12;
    int m    = id % 12;
    int b_a  = id / 288;
    int hd_a = (id / 24) % 12;
    int r_a  = id % 24;
    int b_q  = n / 24;
    int s_q  = n % 24;

    {
        const float4* pe4 = (const float4*)(path ? pey : pex);
        float4* d4 = (float4*)pe_s[path];
        for (int idx = tp; idx < DIM * NPOS / 4; idx += 256)
            d4[idx] = pe4[idx];
    }

    if (!path) {
        const float4* qb = (const float4*)(query + (((size_t)(b_q * 12 + m)) * SEQ + s_q * 24) * DIM);
        for (int idx = tp; idx < HH * DIM / 4; idx += 256) {
            int rr = idx >> 4, c4 = (idx & 15) * 4;
            *(float4*)&q_s[0][rr * 68 + c4] = qb[idx];
        }
    } else {
        const float* qb = query + (((size_t)(b_q * 12 + m)) * SEQ + s_q) * DIM;
        for (int idx = tp; idx < HH * DIM / 4; idx += 256) {
            int rr = idx >> 4, c4 = (idx & 15) * 4;
            *(float4*)&q_s[1][rr * 68 + c4] = *(const float4*)(qb + (size_t)rr * (24 * DIM) + c4);
        }
    }
    __syncthreads();

    for (int o = t; o < 2 * HH * 12; o += 512) {
        int pa  = (o >= 288) ? 1 : 0;
        int rem = o - pa * 288;
        int j   = rem / 12;
        int pp  = rem - j * 12;
        const float4* qr4 = (const float4*)&q_s[pa][j * 68];
        const float*  pr  = pe_s[pa] + 2 * pp;
        unsigned long long acc = 0ull;
        #pragma unroll
        for (int dq = 0; dq < 16; dq++) {
            float4 q4 = qr4[dq];
            float2 v0 = *(const float2*)(pr + (4 * dq + 0) * NPOS);
            float2 v1 = *(const float2*)(pr + (4 * dq + 1) * NPOS);
            float2 v2 = *(const float2*)(pr + (4 * dq + 2) * NPOS);
            float2 v3 = *(const float2*)(pr + (4 * dq + 3) * NPOS);
            acc = fma2(pack2(q4.x, q4.x), pack2(v0.x, v0.y), acc);
            acc = fma2(pack2(q4.y, q4.y), pack2(v1.x, v1.y), acc);
            acc = fma2(pack2(q4.z, q4.z), pack2(v2.x, v2.y), acc);
            acc = fma2(pack2(q4.w, q4.w), pack2(v3.x, v3.y), acc);
        }
        *(float2*)(&li[pa][j * 26 + 2 * pp]) = *(float2*)&acc;
    }
    __syncthreads();

    int w    = (t >> 5) & 7;
    int lane = t & 31;
    int bh   = b_q * 12 + m;
    for (int j = w; j < HH; j += 8) {
        const float* arow;
        int astride;
        float* dst;
        if (!path) {
            arow = attn + (((size_t)(b_a * 12 + hd_a)) * SEQ + (size_t)(r_a * 24 + j)) * SEQ
                        + (size_t)(r_a * 24);
            astride = 1;
            dst = g_Vx + ((size_t)bh * SEQ + (size_t)(s_q * 24 + j)) * NPOS;
        } else {
            arow = attn + (((size_t)(b_a * 12 + hd_a)) * SEQ + (size_t)(j * 24 + r_a)) * SEQ
                        + (size_t)r_a;
            astride = 24;
            dst = g_Vy + ((size_t)bh * SEQ + (size_t)(j * 24 + s_q)) * NPOS;
        }
        float v = 0.0f;
        if (lane < NPOS)
            v = sigmoidf_(arow[lane * astride]);
        #pragma unroll
        for (int d = 1; d < 32; d <<= 1) {
            float tv = __shfl_down_sync(0xffffffffu, v, d);
            if (lane + d < NPOS) v += tv;
        }
        if (lane < NPOS) {
            float pp = fminf(v, (float)(NPOS - 1));
            float pf = floorf(pp);
            int   ifl = (int)pf;
            int   ic  = (int)ceilf(pp);
            float wq  = pp - pf;
            float val = li[path][j * 26 + ic] * wq + li[path][j * 26 + ifl] * (1.0f - wq);
            dst[lane] = val;
        }
    }
}

// ---------------------------------------------------------------------------
// Kernel 2: fused double-cdist + mix via tf32 mma.sync.m16n8k8.
// Block 128 = 4 warps; warp w owns rows 16w..16w+15 of the 64x64 tile.
// Load phase scatters V into FRAGMENT-LINEAR smem (pre-converted to tf32)
// and computes row norms from the SAME truncated values (consistent Gram).
// Mainloop: per path, 3 ksteps x (1 LDS.128 A-frag + 8 x (LDS.64 B-frag + mma)).
// y-path -> xch; x-path combines, diag-zeroes; coalesced writes + mirror.
// ---------------------------------------------------------------------------
__global__ void __launch_bounds__(128) dist_kernel(
    const float* __restrict__ wxp,
    float* __restrict__ out)
{
    // fragment-linear stores: A[path][(mt*3+ks)*32+lane][4], B[path][(nt*3+ks)*32+lane][2]
    __shared__ __align__(16) uint32_t fragA[2][4 * 3 * 32 * 4];   // 6 KB/path
    __shared__ __align__(16) uint32_t fragB[2][8 * 3 * 32 * 2];   // 6 KB/path
    __shared__ float xch[64 * 65];
    __shared__ float nA[2][64];
    __shared__ float nB[2][64];

    int bz = blockIdx.y;
    int u = blockIdx.x;
    int ti = 0;
    #pragma unroll 1
    while (u >= (9 - ti)) { u -= (9 - ti); ti++; }
    int tj = ti + u;
    int p0 = ti * 64;
    int q0 = tj * 64;

    int t    = threadIdx.x;     // 0..127
    int w    = t >> 5;          // warp id = m-tile
    int lane = t & 31;

    // ---- Load + tf32-convert + norm + fragment scatter: 256 tasks ----
    for (int task = t; task < 256; task += 128) {
        int pa = task >> 7;
        int ab = (task >> 6) & 1;
        int r  = task & 63;
        const float* V = pa ? g_Vy : g_Vx;
        const float* src = V + ((size_t)bz * SEQ + (ab ? q0 : p0) + r) * NPOS;
        uint32_t bits[NPOS];
        float nrm = 0.0f;
        #pragma unroll
        for (int i = 0; i < 6; i++) {
            float4 v4 = ((const float4*)src)[i];
            uint32_t b0 = f2tf32(v4.x), b1 = f2tf32(v4.y);
            uint32_t b2 = f2tf32(v4.z), b3 = f2tf32(v4.w);
            bits[4*i+0] = b0; bits[4*i+1] = b1; bits[4*i+2] = b2; bits[4*i+3] = b3;
            float f0 = __uint_as_float(b0), f1 = __uint_as_float(b1);
            float f2v = __uint_as_float(b2), f3 = __uint_as_float(b3);
            nrm = fmaf(f0, f0, nrm); nrm = fmaf(f1, f1, nrm);
            nrm = fmaf(f2v, f2v, nrm); nrm = fmaf(f3, f3, nrm);
        }
        if (!ab) {
            int mt = r >> 4, rr = r & 15;
            #pragma unroll
            for (int k = 0; k < NPOS; k++) {
                int ks = k >> 3, kk = k & 7;
                int ln = ((rr & 7) << 2) | (kk & 3);
                int ai = (rr >> 3) | ((kk >> 2) << 1);
                fragA[pa][(((mt * 3 + ks) * 32 + ln) << 2) + ai] = bits[k];
            }
            nA[pa][r] = nrm;
        } else {
            int nt = r >> 3, nn = r & 7;
            #pragma unroll
            for (int k = 0; k < NPOS; k++) {
                int ks = k >> 3, kk = k & 7;
                int ln = (nn << 2) | (kk & 3);
                int bi = kk >> 2;
                fragB[pa][(((nt * 3 + ks) * 32 + ln) << 1) + bi] = bits[k];
            }
            nB[pa][r] = nrm;
        }
    }
    __syncthreads();

    float wxv = *wxp;
    int rl = lane >> 2;           // 0..7
    int cl = (lane & 3) * 2;      // 0,2,4,6

    // ---- y-path (pa=1) then x-path (pa=0) ----
    #pragma unroll 1
    for (int pa = 1; pa >= 0; pa--) {
        float acc[8][4];
        #pragma unroll
        for (int nt = 0; nt < 8; nt++)
            #pragma unroll
            for (int e = 0; e < 4; e++) acc[nt][e] = 0.0f;

        #pragma unroll
        for (int ks = 0; ks < 3; ks++) {
            uint4 av = *(const uint4*)&fragA[pa][(((w * 3 + ks) * 32 + lane) << 2)];
            uint32_t a[4] = {av.x, av.y, av.z, av.w};
            #pragma unroll
            for (int nt = 0; nt < 8; nt++) {
                uint2 bv = *(const uint2*)&fragB[pa][(((nt * 3 + ks) * 32 + lane) << 1)];
                mma_tf32(acc[nt], a, bv.x, bv.y);
            }
        }

        int r0 = 16 * w + rl;
        if (pa == 1) {
            float scale = 1.0f - wxv;
            float na0 = nA[1][r0], na1 = nA[1][r0 + 8];
            #pragma unroll
            for (int nt = 0; nt < 8; nt++) {
                int c = 8 * nt + cl;
                float nb0 = nB[1][c], nb1 = nB[1][c + 1];
                float d00 = fmaxf(fmaf(-2.0f, acc[nt][0], na0 + nb0), 0.0f);
                float d01 = fmaxf(fmaf(-2.0f, acc[nt][1], na0 + nb1), 0.0f);
                float d10 = fmaxf(fmaf(-2.0f, acc[nt][2], na1 + nb0), 0.0f);
                float d11 = fmaxf(fmaf(-2.0f, acc[nt][3], na1 + nb1), 0.0f);
                xch[r0 * 65 + c]           = scale * fsqrt_approx(d00);
                xch[r0 * 65 + c + 1]       = scale * fsqrt_approx(d01);
                xch[(r0 + 8) * 65 + c]     = scale * fsqrt_approx(d10);
                xch[(r0 + 8) * 65 + c + 1] = scale * fsqrt_approx(d11);
            }
            __syncthreads();
        } else {
            float scale = wxv;
            float na0 = nA[0][r0], na1 = nA[0][r0 + 8];
            #pragma unroll
            for (int nt = 0; nt < 8; nt++) {
                int c = 8 * nt + cl;
                float nb0 = nB[0][c], nb1 = nB[0][c + 1];
                float d00 = fmaxf(fmaf(-2.0f, acc[nt][0], na0 + nb0), 0.0f);
                float d01 = fmaxf(fmaf(-2.0f, acc[nt][1], na0 + nb1), 0.0f);
                float d10 = fmaxf(fmaf(-2.0f, acc[nt][2], na1 + nb0), 0.0f);
                float d11 = fmaxf(fmaf(-2.0f, acc[nt][3], na1 + nb1), 0.0f);
                float f00 = fmaf(scale, fsqrt_approx(d00), xch[r0 * 65 + c]);
                float f01 = fmaf(scale, fsqrt_approx(d01), xch[r0 * 65 + c + 1]);
                float f10 = fmaf(scale, fsqrt_approx(d10), xch[(r0 + 8) * 65 + c]);
                float f11 = fmaf(scale, fsqrt_approx(d11), xch[(r0 + 8) * 65 + c + 1]);
                if (p0 + r0     == q0 + c)     f00 = 0.0f;
                if (p0 + r0     == q0 + c + 1) f01 = 0.0f;
                if (p0 + r0 + 8 == q0 + c)     f10 = 0.0f;
                if (p0 + r0 + 8 == q0 + c + 1) f11 = 0.0f;
                xch[r0 * 65 + c]           = f00;
                xch[r0 * 65 + c + 1]       = f01;
                xch[(r0 + 8) * 65 + c]     = f10;
                xch[(r0 + 8) * 65 + c + 1] = f11;
            }
        }
    }
    __syncthreads();

    // ---- Primary tile: coalesced float4 writes ----
    for (int idx = t; idx < 1024; idx += 128) {
        int r = idx >> 4, c = (idx & 15) * 4;
        const float* xr = &xch[r * 65 + c];
        float4 v = make_float4(xr[0], xr[1], xr[2], xr[3]);
        *(float4*)(out + ((size_t)bz * SEQ + (p0 + r)) * SEQ + q0 + c) = v;
    }

    // ---- Mirror tile for off-diagonal pairs ----
    if (ti != tj) {
        for (int idx = t; idx < 1024; idx += 128) {
            int r = idx >> 4, c = (idx & 15) * 4;
            float4 v = make_float4(xch[(c + 0) * 65 + r],
                                   xch[(c + 1) * 65 + r],
                                   xch[(c + 2) * 65 + r],
                                   xch[(c + 3) * 65 + r]);
            *(float4*)(out + ((size_t)bz * SEQ + (q0 + r)) * SEQ + p0 + c) = v;
        }
    }
}

// ---------------------------------------------------------------------------
extern "C" void kernel_launch(void* const* d_in, const int* in_sizes, int n_in,
                              void* d_out, int out_size) {
    const float* query = (const float*)d_in[0];
    const float* attn  = (const float*)d_in[1];
    const float* pex   = (const float*)d_in[2];
    const float* pey   = (const float*)d_in[3];
    const float* wx    = (const float*)d_in[4];
    float* out = (float*)d_out;

    cope_kernel<<<2304, 512>>>(query, attn, pex, pey);

    dim3 dgrid(45, BATCH);
    dist_kernel<<<dgrid, 128>>>(wx, out);
}

// round 14
// speedup vs baseline: 1.1259x; 1.1259x over previous
#include <cuda_runtime.h>
#include <cstdint>

#define NB      8
#define NHEADS  12
#define HH      24
#define SEQ     576
#define DIM     64
#define NPOS    24
#define BATCH   96
#define KPAD    28          // row stride (words): 16B-aligned; frag reads conflict-free

// Scratch: pe_x_flat / pe_y_flat  [BATCH][SEQ][NPOS]
__device__ __align__(16) float g_Vx[BATCH * SEQ * NPOS];
__device__ __align__(16) float g_Vy[BATCH * SEQ * NPOS];

__device__ __forceinline__ float sigmoidf_(float x) {
    return 1.0f / (1.0f + __expf(-x));
}

__device__ __forceinline__ unsigned long long fma2(unsigned long long a,
                                                   unsigned long long b,
                                                   unsigned long long c) {
    unsigned long long d;
    asm("fma.rn.f32x2 %0, %1, %2, %3;" : "=l"(d) : "l"(a), "l"(b), "l"(c));
    return d;
}

__device__ __forceinline__ unsigned long long pack2(float lo, float hi) {
    unsigned long long r;
    asm("mov.b64 %0, {%1, %2};" : "=l"(r) : "f"(lo), "f"(hi));
    return r;
}

__device__ __forceinline__ float fsqrt_approx(float x) {
    float r;
    asm("sqrt.approx.f32 %0, %1;" : "=f"(r) : "f"(x));
    return r;
}

__device__ __forceinline__ uint32_t f2tf32(float v) {
    uint32_t r;
    asm("cvt.rna.tf32.f32 %0, %1;" : "=r"(r) : "f"(v));
    return r;
}

__device__ __forceinline__ void mma_tf32(float* c, const uint32_t* a, uint32_t b0, uint32_t b1) {
    asm volatile(
        "mma.sync.aligned.m16n8k8.row.col.f32.tf32.tf32.f32 "
        "{%0,%1,%2,%3}, {%4,%5,%6,%7}, {%8,%9}, {%0,%1,%2,%3};"
        : "+f"(c[0]), "+f"(c[1]), "+f"(c[2]), "+f"(c[3])
        : "r"(a[0]), "r"(a[1]), "r"(a[2]), "r"(a[3]), "r"(b0), "r"(b1));
}

// ---------------------------------------------------------------------------
// Kernel 1: fused CoPE (EXACT R12 form — measured ~48 us).
// ---------------------------------------------------------------------------
__global__ void __launch_bounds__(512) cope_kernel(
    const float* __restrict__ query,      // [8,12,576,64]
    const float* __restrict__ attn,       // [8,12,576,576]
    const float* __restrict__ pex,        // [64,24]
    const float* __restrict__ pey)        // [64,24]
{
    __shared__ __align__(16) float q_s[2][HH * 68];
    __shared__ __align__(16) float pe_s[2][DIM * NPOS];
    __shared__ __align__(8)  float li[2][HH * 26];

    int t    = threadIdx.x;
    int path = t >> 8;
    int tp   = t & 255;

    int id   = blockIdx.x;
    int n    = id / 12;
    int m    = id % 12;
    int b_a  = id / 288;
    int hd_a = (id / 24) % 12;
    int r_a  = id % 24;
    int b_q  = n / 24;
    int s_q  = n % 24;

    {
        const float4* pe4 = (const float4*)(path ? pey : pex);
        float4* d4 = (float4*)pe_s[path];
        for (int idx = tp; idx < DIM * NPOS / 4; idx += 256)
            d4[idx] = pe4[idx];
    }

    if (!path) {
        const float4* qb = (const float4*)(query + (((size_t)(b_q * 12 + m)) * SEQ + s_q * 24) * DIM);
        for (int idx = tp; idx < HH * DIM / 4; idx += 256) {
            int rr = idx >> 4, c4 = (idx & 15) * 4;
            *(float4*)&q_s[0][rr * 68 + c4] = qb[idx];
        }
    } else {
        const float* qb = query + (((size_t)(b_q * 12 + m)) * SEQ + s_q) * DIM;
        for (int idx = tp; idx < HH * DIM / 4; idx += 256) {
            int rr = idx >> 4, c4 = (idx & 15) * 4;
            *(float4*)&q_s[1][rr * 68 + c4] = *(const float4*)(qb + (size_t)rr * (24 * DIM) + c4);
        }
    }
    __syncthreads();

    for (int o = t; o < 2 * HH * 12; o += 512) {
        int pa  = (o >= 288) ? 1 : 0;
        int rem = o - pa * 288;
        int j   = rem / 12;
        int pp  = rem - j * 12;
        const float4* qr4 = (const float4*)&q_s[pa][j * 68];
        const float*  pr  = pe_s[pa] + 2 * pp;
        unsigned long long acc = 0ull;
        #pragma unroll
        for (int dq = 0; dq < 16; dq++) {
            float4 q4 = qr4[dq];
            float2 v0 = *(const float2*)(pr + (4 * dq + 0) * NPOS);
            float2 v1 = *(const float2*)(pr + (4 * dq + 1) * NPOS);
            float2 v2 = *(const float2*)(pr + (4 * dq + 2) * NPOS);
            float2 v3 = *(const float2*)(pr + (4 * dq + 3) * NPOS);
            acc = fma2(pack2(q4.x, q4.x), pack2(v0.x, v0.y), acc);
            acc = fma2(pack2(q4.y, q4.y), pack2(v1.x, v1.y), acc);
            acc = fma2(pack2(q4.z, q4.z), pack2(v2.x, v2.y), acc);
            acc = fma2(pack2(q4.w, q4.w), pack2(v3.x, v3.y), acc);
        }
        *(float2*)(&li[pa][j * 26 + 2 * pp]) = *(float2*)&acc;
    }
    __syncthreads();

    int w    = (t >> 5) & 7;
    int lane = t & 31;
    int bh   = b_q * 12 + m;
    for (int j = w; j < HH; j += 8) {
        const float* arow;
        int astride;
        float* dst;
        if (!path) {
            arow = attn + (((size_t)(b_a * 12 + hd_a)) * SEQ + (size_t)(r_a * 24 + j)) * SEQ
                        + (size_t)(r_a * 24);
            astride = 1;
            dst = g_Vx + ((size_t)bh * SEQ + (size_t)(s_q * 24 + j)) * NPOS;
        } else {
            arow = attn + (((size_t)(b_a * 12 + hd_a)) * SEQ + (size_t)(j * 24 + r_a)) * SEQ
                        + (size_t)r_a;
            astride = 24;
            dst = g_Vy + ((size_t)bh * SEQ + (size_t)(j * 24 + s_q)) * NPOS;
        }
        float v = 0.0f;
        if (lane < NPOS)
            v = sigmoidf_(arow[lane * astride]);
        #pragma unroll
        for (int d = 1; d < 32; d <<= 1) {
            float tv = __shfl_down_sync(0xffffffffu, v, d);
            if (lane + d < NPOS) v += tv;
        }
        if (lane < NPOS) {
            float pp = fminf(v, (float)(NPOS - 1));
            float pf = floorf(pp);
            int   ifl = (int)pf;
            int   ic  = (int)ceilf(pp);
            float wq  = pp - pf;
            float val = li[path][j * 26 + ic] * wq + li[path][j * 26 + ifl] * (1.0f - wq);
            dst[lane] = val;
        }
    }
}

// ---------------------------------------------------------------------------
// Kernel 2: fused double-cdist + mix via tf32 mma, fragments read DIRECTLY
// from plain row-major [row][KPAD] smem (scalar LDS, conflict-free:
// bank = 28*(lane>>2)+(lane&3) mod 32 covers all 32 banks).
// Block 128 = 4 warps; warp w owns rows 16w..16w+15; each warp does BOTH
// paths sequentially, y-distances held in registers, combined in-thread.
// xch (output staging) overlays V via union after both mainloops.
// ---------------------------------------------------------------------------
union DistSm {
    float V[2][2][64 * KPAD];   // [path][A=0/B=1][row][k], tf32-truncated values
    float T[64 * 65];
};

__global__ void __launch_bounds__(128) dist_kernel(
    const float* __restrict__ wxp,
    float* __restrict__ out)
{
    __shared__ __align__(16) DistSm sm;
    __shared__ float nrm[2][2][64];

    int bz = blockIdx.y;
    int u = blockIdx.x;
    int ti = 0;
    #pragma unroll 1
    while (u >= (9 - ti)) { u -= (9 - ti); ti++; }
    int tj = ti + u;
    int p0 = ti * 64;
    int q0 = tj * 64;

    int t    = threadIdx.x;     // 0..127
    int w    = t >> 5;          // warp id = m-strip
    int lane = t & 31;

    // ---- Load + tf32 convert: 1536 float4 tasks ----
    for (int task = t; task < 4 * 384; task += 128) {
        int grp = task / 384;           // pa*2 + ab
        int rem = task - grp * 384;
        int pa  = grp >> 1, ab = grp & 1;
        int r   = rem / 6, c4 = (rem - r * 6) * 4;
        const float* V = pa ? g_Vy : g_Vx;
        float4 v4 = *(const float4*)(V + ((size_t)bz * SEQ + (ab ? q0 : p0) + r) * NPOS + c4);
        float4 tv;
        tv.x = __uint_as_float(f2tf32(v4.x));
        tv.y = __uint_as_float(f2tf32(v4.y));
        tv.z = __uint_as_float(f2tf32(v4.z));
        tv.w = __uint_as_float(f2tf32(v4.w));
        *(float4*)&sm.V[pa][ab][r * KPAD + c4] = tv;
    }
    __syncthreads();

    // ---- Norms from the SAME truncated values (consistent Gram) ----
    for (int o = t; o < 256; o += 128) {
        int pa = o >> 7, ab = (o >> 6) & 1, r = o & 63;
        const float* src = sm.V[pa][ab] + r * KPAD;
        float acc = 0.0f;
        #pragma unroll
        for (int k = 0; k < NPOS; k++)
            acc = fmaf(src[k], src[k], acc);
        nrm[pa][ab][r] = acc;
    }
    __syncthreads();

    float wxv = *wxp;
    int rl = lane >> 2;          // 0..7
    int cg = lane & 3;           // threadID in group
    int rowA = 16 * w + rl;

    float res[8][4];

    #pragma unroll 1
    for (int pa = 1; pa >= 0; pa--) {
        const float* As = sm.V[pa][0];
        const float* Bs = sm.V[pa][1];

        float acc[8][4];
        #pragma unroll
        for (int nt = 0; nt < 8; nt++)
            #pragma unroll
            for (int e = 0; e < 4; e++) acc[nt][e] = 0.0f;

        #pragma unroll
        for (int ks = 0; ks < 3; ks++) {
            int kc = 8 * ks + cg;
            uint32_t a[4];
            a[0] = __float_as_uint(As[rowA * KPAD + kc]);
            a[1] = __float_as_uint(As[(rowA + 8) * KPAD + kc]);
            a[2] = __float_as_uint(As[rowA * KPAD + kc + 4]);
            a[3] = __float_as_uint(As[(rowA + 8) * KPAD + kc + 4]);
            #pragma unroll
            for (int nt = 0; nt < 8; nt++) {
                int colB = 8 * nt + rl;
                uint32_t b0 = __float_as_uint(Bs[colB * KPAD + kc]);
                uint32_t b1 = __float_as_uint(Bs[colB * KPAD + kc + 4]);
                mma_tf32(acc[nt], a, b0, b1);
            }
        }

        float na0 = nrm[pa][0][rowA];
        float na1 = nrm[pa][0][rowA + 8];
        if (pa == 1) {
            float scale = 1.0f - wxv;
            #pragma unroll
            for (int nt = 0; nt < 8; nt++) {
                int c = 8 * nt + 2 * cg;
                float nb0 = nrm[1][1][c], nb1 = nrm[1][1][c + 1];
                res[nt][0] = scale * fsqrt_approx(fmaxf(fmaf(-2.0f, acc[nt][0], na0 + nb0), 0.0f));
                res[nt][1] = scale * fsqrt_approx(fmaxf(fmaf(-2.0f, acc[nt][1], na0 + nb1), 0.0f));
                res[nt][2] = scale * fsqrt_approx(fmaxf(fmaf(-2.0f, acc[nt][2], na1 + nb0), 0.0f));
                res[nt][3] = scale * fsqrt_approx(fmaxf(fmaf(-2.0f, acc[nt][3], na1 + nb1), 0.0f));
            }
        } else {
            float scale = wxv;
            #pragma unroll
            for (int nt = 0; nt < 8; nt++) {
                int c = 8 * nt + 2 * cg;
                float nb0 = nrm[0][1][c], nb1 = nrm[0][1][c + 1];
                float f0 = fmaf(scale, fsqrt_approx(fmaxf(fmaf(-2.0f, acc[nt][0], na0 + nb0), 0.0f)), res[nt][0]);
                float f1 = fmaf(scale, fsqrt_approx(fmaxf(fmaf(-2.0f, acc[nt][1], na0 + nb1), 0.0f)), res[nt][1]);
                float f2v = fmaf(scale, fsqrt_approx(fmaxf(fmaf(-2.0f, acc[nt][2], na1 + nb0), 0.0f)), res[nt][2]);
                float f3 = fmaf(scale, fsqrt_approx(fmaxf(fmaf(-2.0f, acc[nt][3], na1 + nb1), 0.0f)), res[nt][3]);
                if (p0 + rowA     == q0 + c)     f0 = 0.0f;
                if (p0 + rowA     == q0 + c + 1) f1 = 0.0f;
                if (p0 + rowA + 8 == q0 + c)     f2v = 0.0f;
                if (p0 + rowA + 8 == q0 + c + 1) f3 = 0.0f;
                res[nt][0] = f0; res[nt][1] = f1; res[nt][2] = f2v; res[nt][3] = f3;
            }
        }
    }
    __syncthreads();   // all V reads complete before T overlays

    // ---- Stage to T (overlay) ----
    {
        int c0 = 2 * cg;
        #pragma unroll
        for (int nt = 0; nt < 8; nt++) {
            int c = 8 * nt + c0;
            sm.T[rowA * 65 + c]           = res[nt][0];
            sm.T[rowA * 65 + c + 1]       = res[nt][1];
            sm.T[(rowA + 8) * 65 + c]     = res[nt][2];
            sm.T[(rowA + 8) * 65 + c + 1] = res[nt][3];
        }
    }
    __syncthreads();

    // ---- Primary tile: coalesced float4 writes ----
    for (int idx = t; idx < 1024; idx += 128) {
        int r = idx >> 4, c = (idx & 15) * 4;
        const float* xr = &sm.T[r * 65 + c];
        float4 v = make_float4(xr[0], xr[1], xr[2], xr[3]);
        *(float4*)(out + ((size_t)bz * SEQ + (p0 + r)) * SEQ + q0 + c) = v;
    }

    // ---- Mirror tile for off-diagonal pairs ----
    if (ti != tj) {
        for (int idx = t; idx < 1024; idx += 128) {
            int r = idx >> 4, c = (idx & 15) * 4;
            float4 v = make_float4(sm.T[(c + 0) * 65 + r],
                                   sm.T[(c + 1) * 65 + r],
                                   sm.T[(c + 2) * 65 + r],
                                   sm.T[(c + 3) * 65 + r]);
            *(float4*)(out + ((size_t)bz * SEQ + (q0 + r)) * SEQ + p0 + c) = v;
        }
    }
}

// ---------------------------------------------------------------------------
extern "C" void kernel_launch(void* const* d_in, const int* in_sizes, int n_in,
                              void* d_out, int out_size) {
    const float* query = (const float*)d_in[0];
    const float* attn  = (const float*)d_in[1];
    const float* pex   = (const float*)d_in[2];
    const float* pey   = (const float*)d_in[3];
    const float* wx    = (const float*)d_in[4];
    float* out = (float*)d_out;

    cope_kernel<<<2304, 512>>>(query, attn, pex, pey);

    dim3 dgrid(45, BATCH);
    dist_kernel<<<dgrid, 128>>>(wx, out);
}